// round 15
// baseline (speedup 1.0000x reference)
#include <cuda_runtime.h>
#include <cuda_fp16.h>
#include <cstdint>

#define NN 20000
// smem float offsets
#define OFF_WBUF0 0        /* 2048 floats (8KB) */
#define OFF_WBUF1 2048     /* 2048 */
#define OFF_FW    4096     /* fp16 feats [4][32][68]h ; later fp32 zT [4][64][34] (8704 floats) */
#define OFF_FN    12800    /* 256 */
#define OFF_Q     13056    /* 256: Q-partial half0 -> tau */
#define OFF_BIAS  13312    /* 384 */
#define OFF_WL1   13696    /* 256 */
#define OFF_C0    13952    /* 16 */
#define OFF_IDX   13968    /* 128 ints */
#define OFF_MBAR  14096    /* 2 x 8B mbarriers */
#define OFF_QP1   14100    /* 256: Q-partial half1 */
#define SM_FLOATS 14356
#define SM_BYTES  (SM_FLOATS * 4)   /* 57424 B -> 4 CTAs/SM */

#define B_BQ  0
#define B_BL2 64
#define B_BV  128
#define B_BK  192
#define B_BW1 256
#define B_BW2 320

#define ZSTR 34

__device__ float g_h[NN * 64];
__device__ uint2 g_wimg[5 * 1024];   // fp16 B-frag images: Wl2, Wk, Ww1, Ww2, Wv

__device__ __forceinline__ uint32_t smem_u32(const void* p) {
    uint32_t a;
    asm("{ .reg .u64 t; cvta.to.shared.u64 t, %1; cvt.u32.u64 %0, t; }" : "=r"(a) : "l"(p));
    return a;
}
__device__ __forceinline__ uint32_t pk2h(float lo, float hi) {
    uint32_t r;
    asm("cvt.rn.f16x2.f32 %0, %1, %2;" : "=r"(r) : "f"(hi), "f"(lo));
    return r;
}
__device__ __forceinline__ void up2h(uint32_t u, float& x0, float& x1) {
    __half2 h = *(__half2*)&u;
    x0 = __low2float(h);
    x1 = __high2float(h);
}
__device__ __forceinline__ void mma16816(float* d, uint32_t a0, uint32_t a1, uint32_t a2,
                                         uint32_t a3, uint32_t b0, uint32_t b1) {
    asm volatile("mma.sync.aligned.m16n8k16.row.col.f32.f16.f16.f32 "
        "{%0,%1,%2,%3}, {%4,%5,%6,%7}, {%8,%9}, {%0,%1,%2,%3};"
        : "+f"(d[0]), "+f"(d[1]), "+f"(d[2]), "+f"(d[3])
        : "r"(a0), "r"(a1), "r"(a2), "r"(a3), "r"(b0), "r"(b1));
}

#define MBAR_INIT(mb, c) asm volatile("mbarrier.init.shared.b64 [%0], %1;" :: "r"(mb), "r"(c) : "memory")
#define MBAR_EXPECT_TX(mb, bytes) \
    asm volatile("mbarrier.arrive.expect_tx.shared.b64 _, [%0], %1;" :: "r"(mb), "r"(bytes) : "memory")
#define FENCE_PA() asm volatile("fence.proxy.async.shared::cta;" ::: "memory")

#define MBAR_WAIT(mb, par) do {                                                \
    asm volatile(                                                              \
        "{\n\t.reg .pred P1;\n\t"                                              \
        "W_%=:\n\t"                                                            \
        "mbarrier.try_wait.parity.shared.b64 P1, [%0], %1;\n\t"                \
        "@P1 bra.uni D_%=;\n\t"                                                \
        "bra.uni W_%=;\n\t"                                                    \
        "D_%=:\n\t}"                                                           \
        :: "r"(mb), "r"(par) : "memory");                                      \
} while (0)

#define BULK_LOAD(IMG, BUFOFF, MBAR)                                           \
    do {                                                                       \
        MBAR_EXPECT_TX((MBAR), 8192);                                          \
        asm volatile(                                                          \
            "cp.async.bulk.shared::cta.global.mbarrier::complete_tx::bytes "   \
            "[%0], [%1], %2, [%3];"                                            \
            :: "r"(sbase + (BUFOFF) * 4), "l"((const void*)(g_wimg + (IMG) * 1024)), \
               "r"(8192), "r"(MBAR) : "memory");                               \
    } while (0)

// nt-split gemm: both mt tiles over 4 nt columns; each B fragment loaded ONCE.
__device__ __forceinline__ void run_gemm_nt4(const uint2* __restrict__ Wb, int lane, int nt0,
                                             const uint32_t A[2][4][4], float D[2][4][4]) {
    #pragma unroll
    for (int mt = 0; mt < 2; mt++)
        #pragma unroll
        for (int n = 0; n < 4; n++)
            #pragma unroll
            for (int e = 0; e < 4; e++) D[mt][n][e] = 0.f;
    #pragma unroll
    for (int n = 0; n < 4; n++) {
        int nt = nt0 + n;
        #pragma unroll
        for (int kt = 0; kt < 4; kt++) {
            uint2 b = Wb[(kt * 8 + nt) * 32 + lane];
            mma16816(D[0][n], A[0][kt][0], A[0][kt][1], A[0][kt][2], A[0][kt][3], b.x, b.y);
            mma16816(D[1][n], A[1][kt][0], A[1][kt][1], A[1][kt][2], A[1][kt][3], b.x, b.y);
        }
    }
}

// pack weights into per-lane fp16 B-fragment images
__global__ void prep_kernel(const float* __restrict__ Wl2, const float* __restrict__ Wk,
                            const float* __restrict__ Ww1, const float* __restrict__ Ww2,
                            const float* __restrict__ Wv) {
    const int g = blockIdx.x;
    const float* W = (g == 0) ? Wl2 : (g == 1) ? Wk : (g == 2) ? Ww1 : (g == 3) ? Ww2 : Wv;
    for (int e = threadIdx.x; e < 1024; e += blockDim.x) {
        int lane = e & 31, tile = e >> 5;
        int kt = tile >> 3, nt = tile & 7;
        int k0 = kt * 16 + (lane & 3) * 2;
        int n = nt * 8 + (lane >> 2);
        uint2 b;
        b.x = pk2h(W[k0 * 64 + n],       W[(k0 + 1) * 64 + n]);
        b.y = pk2h(W[(k0 + 8) * 64 + n], W[(k0 + 9) * 64 + n]);
        g_wimg[g * 1024 + tile * 32 + lane] = b;
    }
}

__global__ void __launch_bounds__(128, 4)
attn_kernel(const float* __restrict__ coords, const float* __restrict__ feats,
            const float* __restrict__ Wq, const float* __restrict__ bq,
            const float* __restrict__ bk, const float* __restrict__ bv,
            const float* __restrict__ Wl1, const float* __restrict__ bl1,
            const float* __restrict__ bl2,
            const float* __restrict__ bw1, const float* __restrict__ bw2,
            const float* __restrict__ g_att, const float* __restrict__ b_att,
            const int* __restrict__ knn)
{
    extern __shared__ float sm[];
    const int tid = threadIdx.x;
    const int w = tid >> 5, lane = tid & 31;
    const int gnode = blockIdx.x * 4 + w;
    const uint32_t sbase = smem_u32(sm);
    const uint32_t mb0 = sbase + OFF_MBAR * 4;
    const uint32_t mb1 = mb0 + 8;
    const uint32_t FULL = 0xffffffffu;
    int* sIdx = (int*)(sm + OFF_IDX);
    uint32_t* fwh = (uint32_t*)(sm + OFF_FW);   // fp16x2 view of feats tile

    if (tid == 0) {
        MBAR_INIT(mb0, 1);
        MBAR_INIT(mb1, 1);
        FENCE_PA();
        BULK_LOAD(0, OFF_WBUF0, mb0);   // Wl2
        BULK_LOAD(1, OFF_WBUF1, mb1);   // Wk
    }

    // ---------- prologue ----------
    const int jn = knn[gnode * 33 + lane];
    sIdx[w * 32 + lane] = jn;
    if (lane < 3) sm[OFF_C0 + w * 4 + lane] = coords[gnode * 3 + lane];
    const float ncx = coords[jn * 3 + 0];
    const float ncy = coords[jn * 3 + 1];
    const float ncz = coords[jn * 3 + 2];
    {
        float2 ff = *(const float2*)&feats[gnode * 64 + lane * 2];
        *(float2*)&sm[OFF_FN + w * 64 + lane * 2] = ff;
    }
    __syncwarp();
    #pragma unroll
    for (int it = 0; it < 16; it++) {   // neighbor feats tile [w][32][68] fp16
        int r = it * 2 + (lane >> 4), c4 = lane & 15;
        int j = sIdx[w * 32 + r];
        float4 v = ((const float4*)feats)[j * 16 + c4];
        uint2 u;
        u.x = pk2h(v.x, v.y);
        u.y = pk2h(v.z, v.w);
        *(uint2*)&fwh[(w * 32 + r) * 34 + c4 * 2] = u;
    }
    for (int e = tid; e < 384; e += 128) {
        int s = e >> 6, c = e & 63;
        sm[OFF_BIAS + e] = (s == 0) ? bq[c] : (s == 1) ? bl2[c] : (s == 2) ? bv[c] :
                           (s == 3) ? bk[c] : (s == 4) ? bw1[c] : bw2[c];
    }
    if (tid < 128) sm[OFF_WL1 + tid] = Wl1[tid];
    if (tid < 64)  { sm[OFF_WL1 + 128 + tid] = Wl1[128 + tid]; sm[OFF_WL1 + 192 + tid] = bl1[tid]; }
    __syncthreads();   // prologue smem + mbar init visible

    // ---------- Q partials: thread (khalf, col) covers all 4 nodes ----------
    {
        const int kh = tid >> 6, c = tid & 63;
        const int k0 = kh * 32;
        float p0 = 0.f, p1 = 0.f, p2 = 0.f, p3 = 0.f;
        #pragma unroll
        for (int k4 = 0; k4 < 32; k4 += 4) {
            float4 f0 = *(const float4*)&sm[OFF_FN + 0 * 64 + k0 + k4];
            float4 f1 = *(const float4*)&sm[OFF_FN + 1 * 64 + k0 + k4];
            float4 f2 = *(const float4*)&sm[OFF_FN + 2 * 64 + k0 + k4];
            float4 f3 = *(const float4*)&sm[OFF_FN + 3 * 64 + k0 + k4];
            float wq0 = Wq[(k0 + k4) * 64 + c];
            float wq1 = Wq[(k0 + k4 + 1) * 64 + c];
            float wq2 = Wq[(k0 + k4 + 2) * 64 + c];
            float wq3 = Wq[(k0 + k4 + 3) * 64 + c];
            p0 = fmaf(f0.x, wq0, fmaf(f0.y, wq1, fmaf(f0.z, wq2, fmaf(f0.w, wq3, p0))));
            p1 = fmaf(f1.x, wq0, fmaf(f1.y, wq1, fmaf(f1.z, wq2, fmaf(f1.w, wq3, p1))));
            p2 = fmaf(f2.x, wq0, fmaf(f2.y, wq1, fmaf(f2.z, wq2, fmaf(f2.w, wq3, p2))));
            p3 = fmaf(f3.x, wq0, fmaf(f3.y, wq1, fmaf(f3.z, wq2, fmaf(f3.w, wq3, p3))));
        }
        const int base = kh ? OFF_QP1 : OFF_Q;
        sm[base + 0 * 64 + c] = p0;
        sm[base + 1 * 64 + c] = p1;
        sm[base + 2 * 64 + c] = p2;
        sm[base + 3 * 64 + c] = p3;
    }
    __syncthreads();   // Q partials visible

    // finalize Q into registers: lane owns cols (2l, 2l+1) of node w
    float qx, qy;
    {
        const int cp = lane * 2;
        float2 a0 = *(float2*)&sm[OFF_Q   + w * 64 + cp];
        float2 a1 = *(float2*)&sm[OFF_QP1 + w * 64 + cp];
        float2 bb = *(float2*)&sm[OFF_BIAS + B_BQ + cp];
        qx = fmaxf(a0.x + a1.x + bb.x, 0.f);
        qy = fmaxf(a0.y + a1.y + bb.y, 0.f);
    }

    // ---------- hid = relu(diff @ Wl1 + bl1) -> curA ----------
    uint32_t curA[2][4][4], peA[2][4][4];
    {
        float c0x = sm[OFF_C0 + w * 4], c0y = sm[OFF_C0 + w * 4 + 1], c0z = sm[OFF_C0 + w * 4 + 2];
        float dx[4], dy[4], dz[4];
        #pragma unroll
        for (int m = 0; m < 4; m++) {
            int row = (lane >> 2) + m * 8;
            dx[m] = __shfl_sync(FULL, ncx, row) - c0x;
            dy[m] = __shfl_sync(FULL, ncy, row) - c0y;
            dz[m] = __shfl_sync(FULL, ncz, row) - c0z;
        }
        #pragma unroll
        for (int kt = 0; kt < 4; kt++)
            #pragma unroll
            for (int half = 0; half < 2; half++) {
                int cc = kt * 16 + 2 * (lane & 3) + 8 * half;
                float2 w0 = *(float2*)&sm[OFF_WL1 + cc];
                float2 w1 = *(float2*)&sm[OFF_WL1 + 64 + cc];
                float2 w2 = *(float2*)&sm[OFF_WL1 + 128 + cc];
                float2 bb = *(float2*)&sm[OFF_WL1 + 192 + cc];
                #pragma unroll
                for (int mt = 0; mt < 2; mt++)
                    #pragma unroll
                    for (int rs = 0; rs < 2; rs++) {
                        int m = mt * 2 + rs;
                        float h0 = fmaxf(fmaf(dx[m], w0.x, fmaf(dy[m], w1.x, fmaf(dz[m], w2.x, bb.x))), 0.f);
                        float h1 = fmaxf(fmaf(dx[m], w0.y, fmaf(dy[m], w1.y, fmaf(dz[m], w2.y, bb.y))), 0.f);
                        curA[mt][kt][half * 2 + rs] = pk2h(h0, h1);
                    }
            }
    }

    float D2[2][4][4];

    // ---- stage 0: fc = hid @ Wl2 + bl2 ; pe = fc + feats[j] -> peA ; fc -> curA (staged) ----
    MBAR_WAIT(mb0, 0);
    {
        uint32_t stash[16];
        #pragma unroll
        for (int h = 0; h < 2; h++) {
            run_gemm_nt4((const uint2*)(sm + OFF_WBUF0), lane, h * 4, curA, D2);
            #pragma unroll
            for (int n = 0; n < 4; n++) {
                int nt = h * 4 + n;
                int cb = nt * 8 + 2 * (lane & 3);
                float2 b2 = *(float2*)&sm[OFF_BIAS + B_BL2 + cb];
                #pragma unroll
                for (int mt = 0; mt < 2; mt++) {
                    int rA = mt * 16 + (lane >> 2);
                    uint32_t fa = fwh[(w * 32 + rA) * 34 + nt * 4 + (lane & 3)];
                    uint32_t fb = fwh[(w * 32 + rA + 8) * 34 + nt * 4 + (lane & 3)];
                    float fax, fay, fbx, fby;
                    up2h(fa, fax, fay);
                    up2h(fb, fbx, fby);
                    float fc0 = D2[mt][n][0] + b2.x, fc1 = D2[mt][n][1] + b2.y;
                    float fc2 = D2[mt][n][2] + b2.x, fc3 = D2[mt][n][3] + b2.y;
                    peA[mt][nt >> 1][(nt & 1) * 2]     = pk2h(fc0 + fax, fc1 + fay);
                    peA[mt][nt >> 1][(nt & 1) * 2 + 1] = pk2h(fc2 + fbx, fc3 + fby);
                    uint32_t u0 = pk2h(fc0, fc1), u1 = pk2h(fc2, fc3);
                    if (h == 0) {
                        stash[mt * 8 + n * 2]     = u0;
                        stash[mt * 8 + n * 2 + 1] = u1;
                    } else {
                        curA[mt][nt >> 1][(nt & 1) * 2]     = u0;
                        curA[mt][nt >> 1][(nt & 1) * 2 + 1] = u1;
                    }
                }
            }
        }
        #pragma unroll
        for (int mt = 0; mt < 2; mt++)
            #pragma unroll
            for (int n = 0; n < 4; n++) {
                curA[mt][n >> 1][(n & 1) * 2]     = stash[mt * 8 + n * 2];
                curA[mt][n >> 1][(n & 1) * 2 + 1] = stash[mt * 8 + n * 2 + 1];
            }
    }
    __syncthreads();                              // all warps done with WBUF0
    if (tid == 0) BULK_LOAD(2, OFF_WBUF0, mb0);   // Ww1 -> buf0

    // ---- stage 1: Kf = pe @ Wk ; rel = (relu(Kf+bk) - Q) * fc -> curA ----
    MBAR_WAIT(mb1, 0);
    #pragma unroll
    for (int h = 0; h < 2; h++) {
        run_gemm_nt4((const uint2*)(sm + OFF_WBUF1), lane, h * 4, peA, D2);
        #pragma unroll
        for (int n = 0; n < 4; n++) {
            int nt = h * 4 + n;
            int cb = nt * 8 + 2 * (lane & 3);
            int srcl = nt * 4 + (lane & 3);
            float2 b2 = *(float2*)&sm[OFF_BIAS + B_BK + cb];
            float q0 = __shfl_sync(FULL, qx, srcl);
            float q1 = __shfl_sync(FULL, qy, srcl);
            #pragma unroll
            for (int mt = 0; mt < 2; mt++) {
                float fc0, fc1, fc2, fc3;
                up2h(curA[mt][nt >> 1][(nt & 1) * 2],     fc0, fc1);
                up2h(curA[mt][nt >> 1][(nt & 1) * 2 + 1], fc2, fc3);
                float r0 = (fmaxf(D2[mt][n][0] + b2.x, 0.f) - q0) * fc0;
                float r1 = (fmaxf(D2[mt][n][1] + b2.y, 0.f) - q1) * fc1;
                float r2 = (fmaxf(D2[mt][n][2] + b2.x, 0.f) - q0) * fc2;
                float r3 = (fmaxf(D2[mt][n][3] + b2.y, 0.f) - q1) * fc3;
                curA[mt][nt >> 1][(nt & 1) * 2]     = pk2h(r0, r1);
                curA[mt][nt >> 1][(nt & 1) * 2 + 1] = pk2h(r2, r3);
            }
        }
    }
    __syncthreads();                              // all warps done with WBUF1
    if (tid == 0) BULK_LOAD(3, OFF_WBUF1, mb1);   // Ww2 -> buf1

    // ---- stage 2: wh = relu(rel @ Ww1 + bw1) -> curA (nt-split, staged) ----
    MBAR_WAIT(mb0, 1);
    {
        uint32_t stash[16];
        #pragma unroll
        for (int h = 0; h < 2; h++) {
            run_gemm_nt4((const uint2*)(sm + OFF_WBUF0), lane, h * 4, curA, D2);
            #pragma unroll
            for (int n = 0; n < 4; n++) {
                int nt = h * 4 + n;
                int cb = nt * 8 + 2 * (lane & 3);
                float2 b2 = *(float2*)&sm[OFF_BIAS + B_BW1 + cb];
                #pragma unroll
                for (int mt = 0; mt < 2; mt++) {
                    uint32_t u0 = pk2h(fmaxf(D2[mt][n][0] + b2.x, 0.f),
                                       fmaxf(D2[mt][n][1] + b2.y, 0.f));
                    uint32_t u1 = pk2h(fmaxf(D2[mt][n][2] + b2.x, 0.f),
                                       fmaxf(D2[mt][n][3] + b2.y, 0.f));
                    if (h == 0) {
                        stash[mt * 8 + n * 2]     = u0;
                        stash[mt * 8 + n * 2 + 1] = u1;
                    } else {
                        curA[mt][nt >> 1][(nt & 1) * 2]     = u0;
                        curA[mt][nt >> 1][(nt & 1) * 2 + 1] = u1;
                    }
                }
            }
        }
        #pragma unroll
        for (int mt = 0; mt < 2; mt++)
            #pragma unroll
            for (int n = 0; n < 4; n++) {
                curA[mt][n >> 1][(n & 1) * 2]     = stash[mt * 8 + n * 2];
                curA[mt][n >> 1][(n & 1) * 2 + 1] = stash[mt * 8 + n * 2 + 1];
            }
    }
    __syncthreads();                              // all warps done with WBUF0
    if (tid == 0) BULK_LOAD(4, OFF_WBUF0, mb0);   // Wv -> buf0

    // ---- stage 3: z = wh @ Ww2 + bw2 -> zT (own warp's FW slice; nt-split) ----
    MBAR_WAIT(mb1, 1);
    #pragma unroll
    for (int h = 0; h < 2; h++) {
        run_gemm_nt4((const uint2*)(sm + OFF_WBUF1), lane, h * 4, curA, D2);
        #pragma unroll
        for (int n = 0; n < 4; n++) {
            int nt = h * 4 + n;
            int cb = nt * 8 + 2 * (lane & 3);
            float2 b2 = *(float2*)&sm[OFF_BIAS + B_BW2 + cb];
            #pragma unroll
            for (int mt = 0; mt < 2; mt++) {
                int rA = mt * 16 + (lane >> 2);
                sm[OFF_FW + (w * 64 + cb)     * ZSTR + rA]     = D2[mt][n][0] + b2.x;
                sm[OFF_FW + (w * 64 + cb + 1) * ZSTR + rA]     = D2[mt][n][1] + b2.y;
                sm[OFF_FW + (w * 64 + cb)     * ZSTR + rA + 8] = D2[mt][n][2] + b2.x;
                sm[OFF_FW + (w * 64 + cb + 1) * ZSTR + rA + 8] = D2[mt][n][3] + b2.y;
            }
        }
    }
    __syncwarp();

    // ---- sparsemax (Michelot fixed point, 4-way split sums): warp w owns node w ----
    #pragma unroll
    for (int p = 0; p < 2; p++) {
        const int col = lane * 2 + p;
        float z[32];
        const float* zp = &sm[OFF_FW + (w * 64 + col) * ZSTR];
        #pragma unroll
        for (int j = 0; j < 16; j++) {
            float2 v = *(const float2*)&zp[j * 2];
            z[2 * j] = v.x; z[2 * j + 1] = v.y;
        }
        float s0 = 0.f, s1 = 0.f, s2 = 0.f, s3 = 0.f;
        #pragma unroll
        for (int k = 0; k < 32; k += 4) {
            s0 += z[k]; s1 += z[k + 1]; s2 += z[k + 2]; s3 += z[k + 3];
        }
        float cnt = 32.f, tau = (((s0 + s1) + (s2 + s3)) - 1.f) * (1.f / 32.f);
        for (int it = 0; it < 32; it++) {
            float n0 = 0.f, n1 = 0.f, n2 = 0.f, n3 = 0.f;
            float c0 = 0.f, c1 = 0.f, c2 = 0.f, c3 = 0.f;
            #pragma unroll
            for (int k = 0; k < 32; k += 4) {
                if (z[k]     > tau) { n0 += z[k];     c0 += 1.f; }
                if (z[k + 1] > tau) { n1 += z[k + 1]; c1 += 1.f; }
                if (z[k + 2] > tau) { n2 += z[k + 2]; c2 += 1.f; }
                if (z[k + 3] > tau) { n3 += z[k + 3]; c3 += 1.f; }
            }
            float ns = (n0 + n1) + (n2 + n3);
            float nc = (c0 + c1) + (c2 + c3);
            if (nc == cnt) break;
            cnt = nc; tau = (ns - 1.f) / nc;
        }
        sm[OFF_Q + w * 64 + col] = tau;   // Q region free after finalize
    }
    __syncwarp();

    // ---- stage 4: V = pe @ Wv + bv ; attn = sum_k relu(z - tau)*V ; LN (nt-split) ----
    MBAR_WAIT(mb0, 0);
    float part[16];
    #pragma unroll
    for (int j = 0; j < 16; j++) part[j] = 0.f;
    #pragma unroll
    for (int h = 0; h < 2; h++) {
        run_gemm_nt4((const uint2*)(sm + OFF_WBUF0), lane, h * 4, peA, D2);
        #pragma unroll
        for (int n = 0; n < 4; n++) {
            int nt = h * 4 + n;
            int cb = nt * 8 + 2 * (lane & 3);
            float2 b2 = *(float2*)&sm[OFF_BIAS + B_BV + cb];
            float2 t2 = *(float2*)&sm[OFF_Q + w * 64 + cb];
            #pragma unroll
            for (int mt = 0; mt < 2; mt++) {
                int rA = mt * 16 + (lane >> 2);
                #pragma unroll
                for (int rs = 0; rs < 2; rs++) {
                    int row = rA + rs * 8;
                    float z0 = sm[OFF_FW + (w * 64 + cb)     * ZSTR + row];
                    float z1 = sm[OFF_FW + (w * 64 + cb + 1) * ZSTR + row];
                    part[nt * 2]     = fmaf(fmaxf(z0 - t2.x, 0.f), D2[mt][n][rs * 2]     + b2.x, part[nt * 2]);
                    part[nt * 2 + 1] = fmaf(fmaxf(z1 - t2.y, 0.f), D2[mt][n][rs * 2 + 1] + b2.y, part[nt * 2 + 1]);
                }
            }
        }
    }
    #pragma unroll
    for (int j = 0; j < 16; j++) {
        float v = part[j];
        v += __shfl_xor_sync(FULL, v, 4);
        v += __shfl_xor_sync(FULL, v, 8);
        v += __shfl_xor_sync(FULL, v, 16);
        part[j] = v;
    }
    float xs[16], tot = 0.f;
    #pragma unroll
    for (int j = 0; j < 16; j++) {
        int col = 8 * (j >> 1) + 2 * (lane & 3) + (j & 1);
        xs[j] = fmaf(2.f, sm[OFF_FN + w * 64 + col], part[j]);
        tot += xs[j];
    }
    #pragma unroll
    for (int off = 16; off > 0; off >>= 1) tot += __shfl_xor_sync(FULL, tot, off);
    const float mean = tot * (1.f / 512.f);
    float vt = 0.f;
    #pragma unroll
    for (int j = 0; j < 16; j++) { float c = xs[j] - mean; vt += c * c; }
    #pragma unroll
    for (int off = 16; off > 0; off >>= 1) vt += __shfl_xor_sync(FULL, vt, off);
    const float rsg = rsqrtf(vt * (1.f / 512.f) + 1e-5f);
    if ((lane >> 2) == 0) {
        #pragma unroll
        for (int j = 0; j < 16; j++) {
            int col = 8 * (j >> 1) + 2 * (lane & 3) + (j & 1);
            g_h[gnode * 64 + col] = fmaf(g_att[col] * (xs[j] - mean), rsg, b_att[col]);
        }
    }
}

// ---------------- GCN + FF + LN : fully warp-local, 4 nodes/warp, float2 ----------------
__global__ __launch_bounds__(64, 16)
void gcn_kernel(const float* __restrict__ coords,
                const float* __restrict__ Wsg, const float* __restrict__ bsg,
                const float* __restrict__ Wf,  const float* __restrict__ bf,
                const float* __restrict__ g_ff, const float* __restrict__ b_ff,
                const int* __restrict__ knn,
                float* __restrict__ out)
{
    const int tid = threadIdx.x;
    const int g = tid >> 5, lane = tid & 31;
    const int i0 = blockIdx.x * 8 + g * 4;   // this warp's 4 nodes
    const int c2 = lane * 2;

    __shared__ int   sIdx[2][4][32];
    __shared__ float sAgg[2][4][68];
    __shared__ float s1[2][4][64];

    #pragma unroll
    for (int n = 0; n < 4; n++)
        sIdx[g][n][lane] = knn[(i0 + n) * 33 + 1 + lane];
    __syncwarp();

    float2 hd[4], a[4];
    #pragma unroll
    for (int n = 0; n < 4; n++) {
        hd[n] = *(const float2*)&g_h[(i0 + n) * 64 + c2];
        a[n] = hd[n];
    }
    #pragma unroll 4
    for (int k = 0; k < 32; k++) {
        #pragma unroll
        for (int n = 0; n < 4; n++) {
            float2 v = *(const float2*)&g_h[sIdx[g][n][k] * 64 + c2];
            a[n].x += v.x; a[n].y += v.y;
        }
    }
    #pragma unroll
    for (int n = 0; n < 4; n++) {
        sAgg[g][n][c2]     = a[n].x * (1.f / 33.f);
        sAgg[g][n][c2 + 1] = a[n].y * (1.f / 33.f);
    }
    if (lane < 12) {
        int n = lane / 3, c = lane - n * 3;
        float cc = coords[(i0 + n) * 3 + c];
        for (int k = 0; k < 32; k++) cc += coords[sIdx[g][n][k] * 3 + c];
        sAgg[g][n][64 + c] = cc * (1.f / 33.f);
    }
    __syncwarp();

    float2 x1[4];
    {
        float2 bb = *(const float2*)&bsg[c2];
        #pragma unroll
        for (int n = 0; n < 4; n++) x1[n] = bb;
    }
    #pragma unroll 4
    for (int j = 0; j < 67; j++) {
        float2 ww = *(const float2*)&Wsg[j * 64 + c2];
        #pragma unroll
        for (int n = 0; n < 4; n++) {
            float s = sAgg[g][n][j];
            x1[n].x = fmaf(s, ww.x, x1[n].x);
            x1[n].y = fmaf(s, ww.y, x1[n].y);
        }
    }
    #pragma unroll
    for (int n = 0; n < 4; n++) {
        s1[g][n][c2]     = fmaxf(x1[n].x, 0.f);
        s1[g][n][c2 + 1] = fmaxf(x1[n].y, 0.f);
    }
    __syncwarp();

    float2 x[4];
    {
        float2 bb = *(const float2*)&bf[c2];
        #pragma unroll
        for (int n = 0; n < 4; n++) x[n] = bb;
    }
    #pragma unroll 4
    for (int j = 0; j < 64; j++) {
        float2 ww = *(const float2*)&Wf[j * 64 + c2];
        #pragma unroll
        for (int n = 0; n < 4; n++) {
            float s = s1[g][n][j];
            x[n].x = fmaf(s, ww.x, x[n].x);
            x[n].y = fmaf(s, ww.y, x[n].y);
        }
    }
    #pragma unroll
    for (int n = 0; n < 4; n++) { x[n].x += hd[n].x; x[n].y += hd[n].y; }

    const float2 gd = *(const float2*)&g_ff[c2];
    const float2 bd = *(const float2*)&b_ff[c2];
    #pragma unroll
    for (int n = 0; n < 4; n++) {
        float s = x[n].x + x[n].y;
        #pragma unroll
        for (int off = 16; off > 0; off >>= 1) s += __shfl_xor_sync(0xffffffffu, s, off);
        const float mean = s * (1.f / 64.f);
        const float cx = x[n].x - mean, cy = x[n].y - mean;
        float v = cx * cx + cy * cy;
        #pragma unroll
        for (int off = 16; off > 0; off >>= 1) v += __shfl_xor_sync(0xffffffffu, v, off);
        const float rs = rsqrtf(v * (1.f / 64.f) + 1e-5f);
        float2 o;
        o.x = fmaf(gd.x * cx, rs, bd.x);
        o.y = fmaf(gd.y * cy, rs, bd.y);
        *(float2*)&out[(i0 + n) * 64 + c2] = o;
    }
}

extern "C" void kernel_launch(void* const* d_in, const int* in_sizes, int n_in,
                              void* d_out, int out_size)
{
    const float* coords = (const float*)d_in[0];
    const float* feats  = (const float*)d_in[1];
    const float* Wq  = (const float*)d_in[2];
    const float* bq  = (const float*)d_in[3];
    const float* Wk  = (const float*)d_in[4];
    const float* bk  = (const float*)d_in[5];
    const float* Wv  = (const float*)d_in[6];
    const float* bv  = (const float*)d_in[7];
    const float* Wl1 = (const float*)d_in[8];
    const float* bl1 = (const float*)d_in[9];
    const float* Wl2 = (const float*)d_in[10];
    const float* bl2 = (const float*)d_in[11];
    const float* Ww1 = (const float*)d_in[12];
    const float* bw1 = (const float*)d_in[13];
    const float* Ww2 = (const float*)d_in[14];
    const float* bw2 = (const float*)d_in[15];
    const float* g_att = (const float*)d_in[16];
    const float* b_att = (const float*)d_in[17];
    const float* Wsg = (const float*)d_in[18];
    const float* bsg = (const float*)d_in[19];
    const float* Wf  = (const float*)d_in[20];
    const float* bf  = (const float*)d_in[21];
    const float* g_ff = (const float*)d_in[22];
    const float* b_ff = (const float*)d_in[23];
    const int*   knn  = (const int*)d_in[24];

    cudaFuncSetAttribute(attn_kernel, cudaFuncAttributeMaxDynamicSharedMemorySize, SM_BYTES);

    prep_kernel<<<5, 256>>>(Wl2, Wk, Ww1, Ww2, Wv);
    attn_kernel<<<NN / 4, 128, SM_BYTES>>>(coords, feats, Wq, bq, bk, bv,
                                           Wl1, bl1, bl2, bw1, bw2,
                                           g_att, b_att, knn);
    gcn_kernel<<<NN / 8, 64>>>(coords, Wsg, bsg, Wf, bf, g_ff, b_ff, knn,
                               (float*)d_out);
}

// round 16
// speedup vs baseline: 1.0745x; 1.0745x over previous
#include <cuda_runtime.h>
#include <cuda_fp16.h>
#include <cstdint>

#define NN 20000
// smem float offsets
#define OFF_WBUF0 0        /* 2048 floats (8KB) */
#define OFF_WBUF1 2048     /* 2048 */
#define OFF_FW    4096     /* feats [4][32][68]=8704 ; later zT [4][64][34]=8704 (per-warp slices) */
#define OFF_FN    12800    /* 256 */
#define OFF_Q     13056    /* 256 (Q, later tau) */
#define OFF_BIAS  13312    /* 384 */
#define OFF_WL1   13696    /* 256 */
#define OFF_C0    13952    /* 16 */
#define OFF_IDX   13968    /* 128 ints */
#define OFF_MBAR  14096    /* 2 x 8B mbarriers (16B) */
#define SM_FLOATS 14100
#define SM_BYTES  (SM_FLOATS * 4)   /* 56400 B -> 4 CTAs/SM */

#define B_BQ  0
#define B_BL2 64
#define B_BV  128
#define B_BK  192
#define B_BW1 256
#define B_BW2 320

#define ZSTR 34

__device__ float g_h[NN * 64];
__device__ uint2 g_wimg[5 * 1024];   // fp16 B-frag images: Wl2, Wk, Ww1, Ww2, Wv

__device__ __forceinline__ uint32_t smem_u32(const void* p) {
    uint32_t a;
    asm("{ .reg .u64 t; cvta.to.shared.u64 t, %1; cvt.u32.u64 %0, t; }" : "=r"(a) : "l"(p));
    return a;
}
__device__ __forceinline__ uint32_t pk2h(float lo, float hi) {
    uint32_t r;
    asm("cvt.rn.f16x2.f32 %0, %1, %2;" : "=r"(r) : "f"(hi), "f"(lo));
    return r;
}
__device__ __forceinline__ void up2h(uint32_t u, float& x0, float& x1) {
    __half2 h = *(__half2*)&u;
    x0 = __low2float(h);
    x1 = __high2float(h);
}
__device__ __forceinline__ void mma16816(float* d, uint32_t a0, uint32_t a1, uint32_t a2,
                                         uint32_t a3, uint32_t b0, uint32_t b1) {
    asm volatile("mma.sync.aligned.m16n8k16.row.col.f32.f16.f16.f32 "
        "{%0,%1,%2,%3}, {%4,%5,%6,%7}, {%8,%9}, {%0,%1,%2,%3};"
        : "+f"(d[0]), "+f"(d[1]), "+f"(d[2]), "+f"(d[3])
        : "r"(a0), "r"(a1), "r"(a2), "r"(a3), "r"(b0), "r"(b1));
}

#define MBAR_INIT(mb, c) asm volatile("mbarrier.init.shared.b64 [%0], %1;" :: "r"(mb), "r"(c) : "memory")
#define MBAR_EXPECT_TX(mb, bytes) \
    asm volatile("mbarrier.arrive.expect_tx.shared.b64 _, [%0], %1;" :: "r"(mb), "r"(bytes) : "memory")
#define FENCE_PA() asm volatile("fence.proxy.async.shared::cta;" ::: "memory")

#define MBAR_WAIT(mb, par) do {                                                \
    asm volatile(                                                              \
        "{\n\t.reg .pred P1;\n\t"                                              \
        "W_%=:\n\t"                                                            \
        "mbarrier.try_wait.parity.shared.b64 P1, [%0], %1;\n\t"                \
        "@P1 bra.uni D_%=;\n\t"                                                \
        "bra.uni W_%=;\n\t"                                                    \
        "D_%=:\n\t}"                                                           \
        :: "r"(mb), "r"(par) : "memory");                                      \
} while (0)

// single-thread 8KB bulk copy of weight image IMG into BUFOFF, completing on MBAR
#define BULK_LOAD(IMG, BUFOFF, MBAR)                                           \
    do {                                                                       \
        MBAR_EXPECT_TX((MBAR), 8192);                                          \
        asm volatile(                                                          \
            "cp.async.bulk.shared::cta.global.mbarrier::complete_tx::bytes "   \
            "[%0], [%1], %2, [%3];"                                            \
            :: "r"(sbase + (BUFOFF) * 4), "l"((const void*)(g_wimg + (IMG) * 1024)), \
               "r"(8192), "r"(MBAR) : "memory");                               \
    } while (0)

// nt-split gemm: both mt tiles over 4 nt columns; each B fragment loaded ONCE.
__device__ __forceinline__ void run_gemm_nt4(const uint2* __restrict__ Wb, int lane, int nt0,
                                             const uint32_t A[2][4][4], float D[2][4][4]) {
    #pragma unroll
    for (int mt = 0; mt < 2; mt++)
        #pragma unroll
        for (int n = 0; n < 4; n++)
            #pragma unroll
            for (int e = 0; e < 4; e++) D[mt][n][e] = 0.f;
    #pragma unroll
    for (int n = 0; n < 4; n++) {
        int nt = nt0 + n;
        #pragma unroll
        for (int kt = 0; kt < 4; kt++) {
            uint2 b = Wb[(kt * 8 + nt) * 32 + lane];
            mma16816(D[0][n], A[0][kt][0], A[0][kt][1], A[0][kt][2], A[0][kt][3], b.x, b.y);
            mma16816(D[1][n], A[1][kt][0], A[1][kt][1], A[1][kt][2], A[1][kt][3], b.x, b.y);
        }
    }
}

// pack weights into per-lane fp16 B-fragment images (wide grid: 1 elem/thread)
__global__ void prep_kernel(const float* __restrict__ Wl2, const float* __restrict__ Wk,
                            const float* __restrict__ Ww1, const float* __restrict__ Ww2,
                            const float* __restrict__ Wv) {
    const int e = blockIdx.x * 128 + threadIdx.x;   // 0..5119
    const int g = e >> 10, idx = e & 1023;
    const float* W = (g == 0) ? Wl2 : (g == 1) ? Wk : (g == 2) ? Ww1 : (g == 3) ? Ww2 : Wv;
    int lane = idx & 31, tile = idx >> 5;
    int kt = tile >> 3, nt = tile & 7;
    int k0 = kt * 16 + (lane & 3) * 2;
    int n = nt * 8 + (lane >> 2);
    uint2 b;
    b.x = pk2h(W[k0 * 64 + n],       W[(k0 + 1) * 64 + n]);
    b.y = pk2h(W[(k0 + 8) * 64 + n], W[(k0 + 9) * 64 + n]);
    g_wimg[g * 1024 + tile * 32 + lane] = b;
}

__global__ void __launch_bounds__(128, 4)
attn_kernel(const float* __restrict__ coords, const float* __restrict__ feats,
            const float* __restrict__ Wq, const float* __restrict__ bq,
            const float* __restrict__ bk, const float* __restrict__ bv,
            const float* __restrict__ Wl1, const float* __restrict__ bl1,
            const float* __restrict__ bl2,
            const float* __restrict__ bw1, const float* __restrict__ bw2,
            const float* __restrict__ g_att, const float* __restrict__ b_att,
            const int* __restrict__ knn)
{
    extern __shared__ float sm[];
    const int tid = threadIdx.x;
    const int w = tid >> 5, lane = tid & 31;
    const int gnode = blockIdx.x * 4 + w;
    const uint32_t sbase = smem_u32(sm);
    const uint32_t mb0 = sbase + OFF_MBAR * 4;
    const uint32_t mb1 = mb0 + 8;
    int* sIdx = (int*)(sm + OFF_IDX);

    // ---------- init mbarriers + kick first two bulk loads ----------
    if (tid == 0) {
        MBAR_INIT(mb0, 1);
        MBAR_INIT(mb1, 1);
        FENCE_PA();
        BULK_LOAD(0, OFF_WBUF0, mb0);   // Wl2
        BULK_LOAD(1, OFF_WBUF1, mb1);   // Wk
    }

    // ---------- prologue ----------
    const int jn = knn[gnode * 33 + lane];
    sIdx[w * 32 + lane] = jn;
    if (lane < 3) sm[OFF_C0 + w * 4 + lane] = coords[gnode * 3 + lane];
    const float ncx = coords[jn * 3 + 0];
    const float ncy = coords[jn * 3 + 1];
    const float ncz = coords[jn * 3 + 2];
    {
        float2 ff = *(const float2*)&feats[gnode * 64 + lane * 2];
        *(float2*)&sm[OFF_FN + w * 64 + lane * 2] = ff;
    }
    __syncwarp();
    #pragma unroll
    for (int it = 0; it < 16; it++) {   // neighbor feats tile [w][32][68]
        int r = it * 2 + (lane >> 4), c4 = lane & 15;
        int j = sIdx[w * 32 + r];
        float4 v = ((const float4*)feats)[j * 16 + c4];
        *(float4*)&sm[OFF_FW + (w * 32 + r) * 68 + c4 * 4] = v;
    }
    for (int e = tid; e < 384; e += 128) {
        int s = e >> 6, c = e & 63;
        sm[OFF_BIAS + e] = (s == 0) ? bq[c] : (s == 1) ? bl2[c] : (s == 2) ? bv[c] :
                           (s == 3) ? bk[c] : (s == 4) ? bw1[c] : bw2[c];
    }
    if (tid < 128) sm[OFF_WL1 + tid] = Wl1[tid];
    if (tid < 64)  { sm[OFF_WL1 + 128 + tid] = Wl1[128 + tid]; sm[OFF_WL1 + 192 + tid] = bl1[tid]; }
    __syncthreads();   // prologue smem + mbar init visible

    // ---------- Q = relu(feats_node @ Wq + bq) : 4-way split accumulators ----------
    {
        const int n2 = tid >> 5, cp = (tid & 31) * 2;
        float a0x = 0.f, a0y = 0.f, a1x = 0.f, a1y = 0.f;
        float a2x = 0.f, a2y = 0.f, a3x = 0.f, a3y = 0.f;
        #pragma unroll
        for (int j = 0; j < 64; j += 4) {
            float f0 = sm[OFF_FN + n2 * 64 + j];
            float f1 = sm[OFF_FN + n2 * 64 + j + 1];
            float f2 = sm[OFF_FN + n2 * 64 + j + 2];
            float f3 = sm[OFF_FN + n2 * 64 + j + 3];
            float2 w0 = *(const float2*)&Wq[j * 64 + cp];
            float2 w1 = *(const float2*)&Wq[(j + 1) * 64 + cp];
            float2 w2 = *(const float2*)&Wq[(j + 2) * 64 + cp];
            float2 w3 = *(const float2*)&Wq[(j + 3) * 64 + cp];
            a0x = fmaf(f0, w0.x, a0x); a0y = fmaf(f0, w0.y, a0y);
            a1x = fmaf(f1, w1.x, a1x); a1y = fmaf(f1, w1.y, a1y);
            a2x = fmaf(f2, w2.x, a2x); a2y = fmaf(f2, w2.y, a2y);
            a3x = fmaf(f3, w3.x, a3x); a3y = fmaf(f3, w3.y, a3y);
        }
        float qx = ((a0x + a1x) + (a2x + a3x)) + sm[OFF_BIAS + B_BQ + cp];
        float qy = ((a0y + a1y) + (a2y + a3y)) + sm[OFF_BIAS + B_BQ + cp + 1];
        sm[OFF_Q + n2 * 64 + cp]     = fmaxf(qx, 0.f);
        sm[OFF_Q + n2 * 64 + cp + 1] = fmaxf(qy, 0.f);
    }

    // ---------- hid = relu(diff @ Wl1 + bl1) -> curA ----------
    uint32_t curA[2][4][4], peA[2][4][4];
    {
        float c0x = sm[OFF_C0 + w * 4], c0y = sm[OFF_C0 + w * 4 + 1], c0z = sm[OFF_C0 + w * 4 + 2];
        float dx[4], dy[4], dz[4];
        #pragma unroll
        for (int m = 0; m < 4; m++) {
            int row = (lane >> 2) + m * 8;
            dx[m] = __shfl_sync(0xffffffffu, ncx, row) - c0x;
            dy[m] = __shfl_sync(0xffffffffu, ncy, row) - c0y;
            dz[m] = __shfl_sync(0xffffffffu, ncz, row) - c0z;
        }
        #pragma unroll
        for (int kt = 0; kt < 4; kt++)
            #pragma unroll
            for (int half = 0; half < 2; half++) {
                int cc = kt * 16 + 2 * (lane & 3) + 8 * half;
                float2 w0 = *(float2*)&sm[OFF_WL1 + cc];
                float2 w1 = *(float2*)&sm[OFF_WL1 + 64 + cc];
                float2 w2 = *(float2*)&sm[OFF_WL1 + 128 + cc];
                float2 bb = *(float2*)&sm[OFF_WL1 + 192 + cc];
                #pragma unroll
                for (int mt = 0; mt < 2; mt++)
                    #pragma unroll
                    for (int rs = 0; rs < 2; rs++) {
                        int m = mt * 2 + rs;
                        float h0 = fmaxf(fmaf(dx[m], w0.x, fmaf(dy[m], w1.x, fmaf(dz[m], w2.x, bb.x))), 0.f);
                        float h1 = fmaxf(fmaf(dx[m], w0.y, fmaf(dy[m], w1.y, fmaf(dz[m], w2.y, bb.y))), 0.f);
                        curA[mt][kt][half * 2 + rs] = pk2h(h0, h1);
                    }
            }
    }

    float D2[2][4][4];

    // ---- stage 0: fc = hid @ Wl2 + bl2 ; pe = fc + feats[j] -> peA ; fc -> curA (staged) ----
    MBAR_WAIT(mb0, 0);
    {
        uint32_t stash[16];
        #pragma unroll
        for (int h = 0; h < 2; h++) {
            run_gemm_nt4((const uint2*)(sm + OFF_WBUF0), lane, h * 4, curA, D2);
            #pragma unroll
            for (int n = 0; n < 4; n++) {
                int nt = h * 4 + n;
                int cb = nt * 8 + 2 * (lane & 3);
                float2 b2 = *(float2*)&sm[OFF_BIAS + B_BL2 + cb];
                #pragma unroll
                for (int mt = 0; mt < 2; mt++) {
                    int rA = mt * 16 + (lane >> 2);
                    float2 fA = *(float2*)&sm[OFF_FW + (w * 32 + rA) * 68 + cb];
                    float2 fB = *(float2*)&sm[OFF_FW + (w * 32 + rA + 8) * 68 + cb];
                    float fc0 = D2[mt][n][0] + b2.x, fc1 = D2[mt][n][1] + b2.y;
                    float fc2 = D2[mt][n][2] + b2.x, fc3 = D2[mt][n][3] + b2.y;
                    peA[mt][nt >> 1][(nt & 1) * 2]     = pk2h(fc0 + fA.x, fc1 + fA.y);
                    peA[mt][nt >> 1][(nt & 1) * 2 + 1] = pk2h(fc2 + fB.x, fc3 + fB.y);
                    uint32_t u0 = pk2h(fc0, fc1), u1 = pk2h(fc2, fc3);
                    if (h == 0) {
                        stash[mt * 8 + n * 2]     = u0;
                        stash[mt * 8 + n * 2 + 1] = u1;
                    } else {
                        curA[mt][nt >> 1][(nt & 1) * 2]     = u0;
                        curA[mt][nt >> 1][(nt & 1) * 2 + 1] = u1;
                    }
                }
            }
        }
        #pragma unroll
        for (int mt = 0; mt < 2; mt++)
            #pragma unroll
            for (int n = 0; n < 4; n++) {
                curA[mt][n >> 1][(n & 1) * 2]     = stash[mt * 8 + n * 2];
                curA[mt][n >> 1][(n & 1) * 2 + 1] = stash[mt * 8 + n * 2 + 1];
            }
    }
    __syncthreads();                              // all warps done with WBUF0
    if (tid == 0) BULK_LOAD(2, OFF_WBUF0, mb0);   // Ww1 -> buf0

    // ---- stage 1: Kf = pe @ Wk ; rel = (relu(Kf+bk) - Q) * fc -> curA (fc from curA) ----
    MBAR_WAIT(mb1, 0);
    #pragma unroll
    for (int h = 0; h < 2; h++) {
        run_gemm_nt4((const uint2*)(sm + OFF_WBUF1), lane, h * 4, peA, D2);
        #pragma unroll
        for (int n = 0; n < 4; n++) {
            int nt = h * 4 + n;
            int cb = nt * 8 + 2 * (lane & 3);
            float2 b2 = *(float2*)&sm[OFF_BIAS + B_BK + cb];
            float2 q2 = *(float2*)&sm[OFF_Q + w * 64 + cb];
            #pragma unroll
            for (int mt = 0; mt < 2; mt++) {
                float fc0, fc1, fc2, fc3;
                up2h(curA[mt][nt >> 1][(nt & 1) * 2],     fc0, fc1);
                up2h(curA[mt][nt >> 1][(nt & 1) * 2 + 1], fc2, fc3);
                float r0 = (fmaxf(D2[mt][n][0] + b2.x, 0.f) - q2.x) * fc0;
                float r1 = (fmaxf(D2[mt][n][1] + b2.y, 0.f) - q2.y) * fc1;
                float r2 = (fmaxf(D2[mt][n][2] + b2.x, 0.f) - q2.x) * fc2;
                float r3 = (fmaxf(D2[mt][n][3] + b2.y, 0.f) - q2.y) * fc3;
                curA[mt][nt >> 1][(nt & 1) * 2]     = pk2h(r0, r1);
                curA[mt][nt >> 1][(nt & 1) * 2 + 1] = pk2h(r2, r3);
            }
        }
    }
    __syncthreads();                              // all warps done with WBUF1
    if (tid == 0) BULK_LOAD(3, OFF_WBUF1, mb1);   // Ww2 -> buf1

    // ---- stage 2: wh = relu(rel @ Ww1 + bw1) -> curA (nt-split, staged) ----
    MBAR_WAIT(mb0, 1);
    {
        uint32_t stash[16];
        #pragma unroll
        for (int h = 0; h < 2; h++) {
            run_gemm_nt4((const uint2*)(sm + OFF_WBUF0), lane, h * 4, curA, D2);
            #pragma unroll
            for (int n = 0; n < 4; n++) {
                int nt = h * 4 + n;
                int cb = nt * 8 + 2 * (lane & 3);
                float2 b2 = *(float2*)&sm[OFF_BIAS + B_BW1 + cb];
                #pragma unroll
                for (int mt = 0; mt < 2; mt++) {
                    uint32_t u0 = pk2h(fmaxf(D2[mt][n][0] + b2.x, 0.f),
                                       fmaxf(D2[mt][n][1] + b2.y, 0.f));
                    uint32_t u1 = pk2h(fmaxf(D2[mt][n][2] + b2.x, 0.f),
                                       fmaxf(D2[mt][n][3] + b2.y, 0.f));
                    if (h == 0) {
                        stash[mt * 8 + n * 2]     = u0;
                        stash[mt * 8 + n * 2 + 1] = u1;
                    } else {
                        curA[mt][nt >> 1][(nt & 1) * 2]     = u0;
                        curA[mt][nt >> 1][(nt & 1) * 2 + 1] = u1;
                    }
                }
            }
        }
        #pragma unroll
        for (int mt = 0; mt < 2; mt++)
            #pragma unroll
            for (int n = 0; n < 4; n++) {
                curA[mt][n >> 1][(n & 1) * 2]     = stash[mt * 8 + n * 2];
                curA[mt][n >> 1][(n & 1) * 2 + 1] = stash[mt * 8 + n * 2 + 1];
            }
    }
    __syncthreads();                              // all warps done with WBUF0
    if (tid == 0) BULK_LOAD(4, OFF_WBUF0, mb0);   // Wv -> buf0

    // ---- stage 3: z = wh @ Ww2 + bw2 -> zT (own warp's FW slice; nt-split) ----
    MBAR_WAIT(mb1, 1);
    #pragma unroll
    for (int h = 0; h < 2; h++) {
        run_gemm_nt4((const uint2*)(sm + OFF_WBUF1), lane, h * 4, curA, D2);
        #pragma unroll
        for (int n = 0; n < 4; n++) {
            int nt = h * 4 + n;
            int cb = nt * 8 + 2 * (lane & 3);
            float2 b2 = *(float2*)&sm[OFF_BIAS + B_BW2 + cb];
            #pragma unroll
            for (int mt = 0; mt < 2; mt++) {
                int rA = mt * 16 + (lane >> 2);
                sm[OFF_FW + (w * 64 + cb)     * ZSTR + rA]     = D2[mt][n][0] + b2.x;
                sm[OFF_FW + (w * 64 + cb + 1) * ZSTR + rA]     = D2[mt][n][1] + b2.y;
                sm[OFF_FW + (w * 64 + cb)     * ZSTR + rA + 8] = D2[mt][n][2] + b2.x;
                sm[OFF_FW + (w * 64 + cb + 1) * ZSTR + rA + 8] = D2[mt][n][3] + b2.y;
            }
        }
    }
    __syncwarp();

    // ---- sparsemax (Michelot fixed point, 4-way split sums): warp w owns node w ----
    #pragma unroll
    for (int p = 0; p < 2; p++) {
        const int col = lane * 2 + p;
        float z[32];
        const float* zp = &sm[OFF_FW + (w * 64 + col) * ZSTR];
        #pragma unroll
        for (int j = 0; j < 16; j++) {
            float2 v = *(const float2*)&zp[j * 2];
            z[2 * j] = v.x; z[2 * j + 1] = v.y;
        }
        float s0 = 0.f, s1 = 0.f, s2 = 0.f, s3 = 0.f;
        #pragma unroll
        for (int k = 0; k < 32; k += 4) {
            s0 += z[k]; s1 += z[k + 1]; s2 += z[k + 2]; s3 += z[k + 3];
        }
        float cnt = 32.f, tau = (((s0 + s1) + (s2 + s3)) - 1.f) * (1.f / 32.f);
        for (int it = 0; it < 32; it++) {
            float n0 = 0.f, n1 = 0.f, n2 = 0.f, n3 = 0.f;
            float c0 = 0.f, c1 = 0.f, c2 = 0.f, c3 = 0.f;
            #pragma unroll
            for (int k = 0; k < 32; k += 4) {
                if (z[k]     > tau) { n0 += z[k];     c0 += 1.f; }
                if (z[k + 1] > tau) { n1 += z[k + 1]; c1 += 1.f; }
                if (z[k + 2] > tau) { n2 += z[k + 2]; c2 += 1.f; }
                if (z[k + 3] > tau) { n3 += z[k + 3]; c3 += 1.f; }
            }
            float ns = (n0 + n1) + (n2 + n3);
            float nc = (c0 + c1) + (c2 + c3);
            if (nc == cnt) break;
            cnt = nc; tau = (ns - 1.f) / nc;
        }
        sm[OFF_Q + w * 64 + col] = tau;   // Q region reused (Q reads finished in stage 1)
    }
    __syncwarp();

    // ---- stage 4: V = pe @ Wv + bv ; attn = sum_k relu(z - tau)*V ; LN (nt-split) ----
    MBAR_WAIT(mb0, 0);
    float part[16];
    #pragma unroll
    for (int j = 0; j < 16; j++) part[j] = 0.f;
    #pragma unroll
    for (int h = 0; h < 2; h++) {
        run_gemm_nt4((const uint2*)(sm + OFF_WBUF0), lane, h * 4, peA, D2);
        #pragma unroll
        for (int n = 0; n < 4; n++) {
            int nt = h * 4 + n;
            int cb = nt * 8 + 2 * (lane & 3);
            float2 b2 = *(float2*)&sm[OFF_BIAS + B_BV + cb];
            float2 t2 = *(float2*)&sm[OFF_Q + w * 64 + cb];
            #pragma unroll
            for (int mt = 0; mt < 2; mt++) {
                int rA = mt * 16 + (lane >> 2);
                #pragma unroll
                for (int rs = 0; rs < 2; rs++) {
                    int row = rA + rs * 8;
                    float z0 = sm[OFF_FW + (w * 64 + cb)     * ZSTR + row];
                    float z1 = sm[OFF_FW + (w * 64 + cb + 1) * ZSTR + row];
                    part[nt * 2]     = fmaf(fmaxf(z0 - t2.x, 0.f), D2[mt][n][rs * 2]     + b2.x, part[nt * 2]);
                    part[nt * 2 + 1] = fmaf(fmaxf(z1 - t2.y, 0.f), D2[mt][n][rs * 2 + 1] + b2.y, part[nt * 2 + 1]);
                }
            }
        }
    }
    #pragma unroll
    for (int j = 0; j < 16; j++) {
        float v = part[j];
        v += __shfl_xor_sync(0xffffffffu, v, 4);
        v += __shfl_xor_sync(0xffffffffu, v, 8);
        v += __shfl_xor_sync(0xffffffffu, v, 16);
        part[j] = v;
    }
    float xs[16], tot = 0.f;
    #pragma unroll
    for (int j = 0; j < 16; j++) {
        int col = 8 * (j >> 1) + 2 * (lane & 3) + (j & 1);
        xs[j] = fmaf(2.f, sm[OFF_FN + w * 64 + col], part[j]);
        tot += xs[j];
    }
    #pragma unroll
    for (int off = 16; off > 0; off >>= 1) tot += __shfl_xor_sync(0xffffffffu, tot, off);
    const float mean = tot * (1.f / 512.f);
    float vt = 0.f;
    #pragma unroll
    for (int j = 0; j < 16; j++) { float c = xs[j] - mean; vt += c * c; }
    #pragma unroll
    for (int off = 16; off > 0; off >>= 1) vt += __shfl_xor_sync(0xffffffffu, vt, off);
    const float rsg = rsqrtf(vt * (1.f / 512.f) + 1e-5f);
    if ((lane >> 2) == 0) {
        #pragma unroll
        for (int j = 0; j < 16; j++) {
            int col = 8 * (j >> 1) + 2 * (lane & 3) + (j & 1);
            g_h[gnode * 64 + col] = fmaf(g_att[col] * (xs[j] - mean), rsg, b_att[col]);
        }
    }
}

// ---------------- GCN + FF + LN : 8 nodes per 64-thread block ----------------
__global__ __launch_bounds__(64, 16)
void gcn_kernel(const float* __restrict__ coords,
                const float* __restrict__ Wsg, const float* __restrict__ bsg,
                const float* __restrict__ Wf,  const float* __restrict__ bf,
                const float* __restrict__ g_ff, const float* __restrict__ b_ff,
                const int* __restrict__ knn,
                float* __restrict__ out)
{
    const int i0 = blockIdx.x * 8;
    const int d = threadIdx.x;
    const int wid = d >> 5, lane = d & 31;

    __shared__ int   sIdx[8][32];
    __shared__ float sAgg[8][68];
    __shared__ float s1[8][64];
    __shared__ float red[8][2];

    #pragma unroll
    for (int t = 0; t < 4; t++) {
        int e = d + t * 64;
        sIdx[e >> 5][e & 31] = knn[(i0 + (e >> 5)) * 33 + 1 + (e & 31)];
    }
    __syncthreads();

    float hd[8], a[8];
    #pragma unroll
    for (int n = 0; n < 8; n++) { hd[n] = g_h[(i0 + n) * 64 + d]; a[n] = hd[n]; }
    #pragma unroll 4
    for (int k = 0; k < 32; k++) {
        #pragma unroll
        for (int n = 0; n < 8; n++) a[n] += g_h[sIdx[n][k] * 64 + d];
    }
    #pragma unroll
    for (int n = 0; n < 8; n++) sAgg[n][d] = a[n] * (1.f / 33.f);
    if (d < 24) {
        int n = d / 3, c = d - n * 3;
        float cc = coords[(i0 + n) * 3 + c];
        for (int k = 0; k < 32; k++) cc += coords[sIdx[n][k] * 3 + c];
        sAgg[n][64 + c] = cc * (1.f / 33.f);
    }
    __syncthreads();

    float x1[8];
    {
        float bb = bsg[d];
        #pragma unroll
        for (int n = 0; n < 8; n++) x1[n] = bb;
    }
    #pragma unroll 4
    for (int j = 0; j < 67; j++) {
        float ww = Wsg[j * 64 + d];
        #pragma unroll
        for (int n = 0; n < 8; n++) x1[n] = fmaf(sAgg[n][j], ww, x1[n]);
    }
    #pragma unroll
    for (int n = 0; n < 8; n++) s1[n][d] = fmaxf(x1[n], 0.f);
    __syncthreads();

    float x[8];
    {
        float bb = bf[d];
        #pragma unroll
        for (int n = 0; n < 8; n++) x[n] = bb;
    }
    #pragma unroll 4
    for (int j = 0; j < 64; j++) {
        float ww = Wf[j * 64 + d];
        #pragma unroll
        for (int n = 0; n < 8; n++) x[n] = fmaf(s1[n][j], ww, x[n]);
    }
    #pragma unroll
    for (int n = 0; n < 8; n++) x[n] += hd[n];

    #pragma unroll
    for (int n = 0; n < 8; n++) {
        float r = x[n];
        #pragma unroll
        for (int off = 16; off > 0; off >>= 1) r += __shfl_xor_sync(0xffffffffu, r, off);
        if (lane == 0) red[n][wid] = r;
    }
    __syncthreads();
    float cv[8];
    #pragma unroll
    for (int n = 0; n < 8; n++)
        cv[n] = x[n] - (red[n][0] + red[n][1]) * (1.f / 64.f);
    __syncthreads();
    #pragma unroll
    for (int n = 0; n < 8; n++) {
        float r = cv[n] * cv[n];
        #pragma unroll
        for (int off = 16; off > 0; off >>= 1) r += __shfl_xor_sync(0xffffffffu, r, off);
        if (lane == 0) red[n][wid] = r;
    }
    __syncthreads();
    const float gd = g_ff[d], bd = b_ff[d];
    #pragma unroll
    for (int n = 0; n < 8; n++) {
        float var = (red[n][0] + red[n][1]) * (1.f / 64.f);
        out[(i0 + n) * 64 + d] = fmaf(gd * cv[n], rsqrtf(var + 1e-5f), bd);
    }
}

extern "C" void kernel_launch(void* const* d_in, const int* in_sizes, int n_in,
                              void* d_out, int out_size)
{
    const float* coords = (const float*)d_in[0];
    const float* feats  = (const float*)d_in[1];
    const float* Wq  = (const float*)d_in[2];
    const float* bq  = (const float*)d_in[3];
    const float* Wk  = (const float*)d_in[4];
    const float* bk  = (const float*)d_in[5];
    const float* Wv  = (const float*)d_in[6];
    const float* bv  = (const float*)d_in[7];
    const float* Wl1 = (const float*)d_in[8];
    const float* bl1 = (const float*)d_in[9];
    const float* Wl2 = (const float*)d_in[10];
    const float* bl2 = (const float*)d_in[11];
    const float* Ww1 = (const float*)d_in[12];
    const float* bw1 = (const float*)d_in[13];
    const float* Ww2 = (const float*)d_in[14];
    const float* bw2 = (const float*)d_in[15];
    const float* g_att = (const float*)d_in[16];
    const float* b_att = (const float*)d_in[17];
    const float* Wsg = (const float*)d_in[18];
    const float* bsg = (const float*)d_in[19];
    const float* Wf  = (const float*)d_in[20];
    const float* bf  = (const float*)d_in[21];
    const float* g_ff = (const float*)d_in[22];
    const float* b_ff = (const float*)d_in[23];
    const int*   knn  = (const int*)d_in[24];

    cudaFuncSetAttribute(attn_kernel, cudaFuncAttributeMaxDynamicSharedMemorySize, SM_BYTES);

    prep_kernel<<<40, 128>>>(Wl2, Wk, Ww1, Ww2, Wv);
    attn_kernel<<<NN / 4, 128, SM_BYTES>>>(coords, feats, Wq, bq, bk, bv,
                                           Wl1, bl1, bl2, bw1, bw2,
                                           g_att, b_att, knn);
    gcn_kernel<<<NN / 8, 64>>>(coords, Wsg, bsg, Wf, bf, g_ff, b_ff, knn,
                               (float*)d_out);
}